// round 11
// baseline (speedup 1.0000x reference)
#include <cuda_runtime.h>
#include <math.h>

// Diffusion: out = expm(-max(t,1e-8)*L) @ x, L = graph Laplacian (~32 nnz/row).
// Chebyshev expansion of e^{-t*lambda} on [0, lambda_ub], fp32 sparse matvecs,
// ONE persistent kernel. R10: nnz-balanced execution.
//   Rows are counting-sorted by nnz in-kernel; the 128-thread group G processes
//   rows rank(G) and rank(2047-G) as ONE concatenated neighbor list
//   (cA+cB ~ const) -> every group does the same number of gather batches, so
//   grid barriers no longer wait on the heaviest row (~45% idle removed).
//   Rank assignment via atomics is nondeterministic, but each row's arithmetic
//   (its own ELL list, same order) is identical whoever computes it -> output
//   bitwise deterministic.

#define NN   2048
#define DD   512
#define ELLW 96           // max off-diag nnz per row (mean ~32, max ~60)
#define MMAX 48
#define THREADS 1024
#define GRID 128          // 1 block/SM
#define GPB  8            // pair-groups per block (128 threads each)
#define NB   97           // histogram bins: cnt in [0, 96]

// -------- device-global scratch (no allocations allowed) --------
__device__ float g_T1[NN * DD];
__device__ float g_T2[NN * DD];
__device__ int2  g_ell[NN * ELLW];
__device__ float g_diag[NN];
__device__ int   g_cnt[NN];
__device__ int   g_hist[NB];
__device__ int   g_offs[NB];
__device__ int   g_perm[NN];
__device__ float g_bmax[GRID];
__device__ float g_bmer[GRID];
__device__ float g_bam [GRID];

__device__ int          g_bar_count = 0;
__device__ volatile int g_bar_gen   = 0;

__device__ __forceinline__ float4 f4_load(const float* p) {
    return *reinterpret_cast<const float4*>(p);
}
__device__ __forceinline__ void f4_store(float* p, float4 v) {
    *reinterpret_cast<float4*>(p) = v;
}

__device__ __forceinline__ void grid_barrier() {
    __threadfence();
    __syncthreads();
    if (threadIdx.x == 0) {
        int gen = g_bar_gen;
        if (atomicAdd(&g_bar_count, 1) == GRID - 1) {
            g_bar_count = 0;
            __threadfence();
            g_bar_gen = gen + 1;
        } else {
            while (g_bar_gen == gen) __nanosleep(64);
        }
        __threadfence();
    }
    __syncthreads();
}

// ---------------------------------------------------------------------------
// Pair SpMV: concatenated list (entries [0,cA) -> row A, [cA,tot) -> row B),
// 4 channels per thread, batch-4 neighbors (4 independent LDG.128, all
// lane-contiguous 512B warp segments). Tag branch is warp-uniform.
// ---------------------------------------------------------------------------
__device__ __forceinline__ void spmv_pair(const float* __restrict__ Y, int ch,
                                          const int2* __restrict__ se,
                                          int cA, int tot,
                                          float accA[4], float accB[4]) {
    int k = 0;
    for (; k + 4 <= tot; k += 4) {
        int2 e0 = se[k], e1 = se[k + 1], e2 = se[k + 2], e3 = se[k + 3];
        float4 y0 = f4_load(Y + (e0.x << 9) + ch);
        float4 y1 = f4_load(Y + (e1.x << 9) + ch);
        float4 y2 = f4_load(Y + (e2.x << 9) + ch);
        float4 y3 = f4_load(Y + (e3.x << 9) + ch);
        float v0 = __int_as_float(e0.y), v1 = __int_as_float(e1.y);
        float v2 = __int_as_float(e2.y), v3 = __int_as_float(e3.y);
        if (k     < cA) { accA[0]-=v0*y0.x; accA[1]-=v0*y0.y; accA[2]-=v0*y0.z; accA[3]-=v0*y0.w; }
        else            { accB[0]-=v0*y0.x; accB[1]-=v0*y0.y; accB[2]-=v0*y0.z; accB[3]-=v0*y0.w; }
        if (k + 1 < cA) { accA[0]-=v1*y1.x; accA[1]-=v1*y1.y; accA[2]-=v1*y1.z; accA[3]-=v1*y1.w; }
        else            { accB[0]-=v1*y1.x; accB[1]-=v1*y1.y; accB[2]-=v1*y1.z; accB[3]-=v1*y1.w; }
        if (k + 2 < cA) { accA[0]-=v2*y2.x; accA[1]-=v2*y2.y; accA[2]-=v2*y2.z; accA[3]-=v2*y2.w; }
        else            { accB[0]-=v2*y2.x; accB[1]-=v2*y2.y; accB[2]-=v2*y2.z; accB[3]-=v2*y2.w; }
        if (k + 3 < cA) { accA[0]-=v3*y3.x; accA[1]-=v3*y3.y; accA[2]-=v3*y3.z; accA[3]-=v3*y3.w; }
        else            { accB[0]-=v3*y3.x; accB[1]-=v3*y3.y; accB[2]-=v3*y3.z; accB[3]-=v3*y3.w; }
    }
    for (; k < tot; k++) {
        int2 e0 = se[k];
        float v0 = __int_as_float(e0.y);
        float4 y0 = f4_load(Y + (e0.x << 9) + ch);
        if (k < cA) { accA[0]-=v0*y0.x; accA[1]-=v0*y0.y; accA[2]-=v0*y0.z; accA[3]-=v0*y0.w; }
        else        { accB[0]-=v0*y0.x; accB[1]-=v0*y0.y; accB[2]-=v0*y0.z; accB[3]-=v0*y0.w; }
    }
}

// ---------------------------------------------------------------------------
__global__ void __launch_bounds__(THREADS, 1)
cheb_all(const float* __restrict__ X, const float* __restrict__ L,
         const float* __restrict__ t_in, float* __restrict__ out) {
    const int tid = threadIdx.x;
    const int blk = blockIdx.x;

    // extraction view: 16 own rows, 64 threads each
    const int rl   = tid >> 6;
    const int lane = tid & 63;
    const int wir  = lane >> 5;
    const int erow = blk * 16 + rl;

    __shared__ int2   s_ell[GPB][2 * ELLW];     // pair lists (12 KB)
    __shared__ float4 s_ykm1[GPB * 2][DD / 4];  // T_{j-2} per row slot (32 KB)
    __shared__ int    s_scan[128];
    __shared__ float  s_diagE[16];
    __shared__ int    s_cntE[16];
    __shared__ int    s_wt[16][2];
    __shared__ float  s_red[16][4];
    __shared__ float  s_coef[MMAX + 1];
    __shared__ float  s_a;
    __shared__ int    s_deg;
    __shared__ double s_c[MMAX + 1];

    if (tid < NB) g_hist[tid] = 0;   // every block writes 0: benign race

    // ============ A) extract own 16 rows of dense L -> global ELL
    const float4* Lr4 = reinterpret_cast<const float4*>(L + (size_t)erow * NN) + lane * 8;
    int   cnt = 0;
    float dv  = 0.f;
#pragma unroll
    for (int k = 0; k < 8; k++) {
        float4 v = Lr4[k];
        int c = lane * 32 + k * 4;
        if (c + 0 == erow) dv = v.x; else cnt += (v.x != 0.f);
        if (c + 1 == erow) dv = v.y; else cnt += (v.y != 0.f);
        if (c + 2 == erow) dv = v.z; else cnt += (v.z != 0.f);
        if (c + 3 == erow) dv = v.w; else cnt += (v.w != 0.f);
    }
    int inc = cnt;
#pragma unroll
    for (int off = 1; off < 32; off <<= 1) {
        int n = __shfl_up_sync(0xffffffffu, inc, off);
        if ((lane & 31) >= off) inc += n;
    }
    if ((lane & 31) == 31) s_wt[rl][wir] = inc;
    __syncthreads();
    int offset = inc - cnt + (wir ? s_wt[rl][0] : 0);
    int total  = s_wt[rl][0] + s_wt[rl][1];
    {
        int o = offset;
        int2* er = g_ell + (size_t)erow * ELLW;
#pragma unroll
        for (int k = 0; k < 8; k++) {
            float4 v = Lr4[k];
            int c = lane * 32 + k * 4;
            if (v.x != 0.f && c + 0 != erow && o < ELLW) { er[o] = make_int2(c + 0, __float_as_int(-v.x)); o++; }
            if (v.y != 0.f && c + 1 != erow && o < ELLW) { er[o] = make_int2(c + 1, __float_as_int(-v.y)); o++; }
            if (v.z != 0.f && c + 2 != erow && o < ELLW) { er[o] = make_int2(c + 2, __float_as_int(-v.z)); o++; }
            if (v.w != 0.f && c + 3 != erow && o < ELLW) { er[o] = make_int2(c + 3, __float_as_int(-v.w)); o++; }
        }
    }
    if (lane == (erow >> 5)) s_diagE[rl] = dv;
    if (lane == 0) s_cntE[rl] = (total < ELLW) ? total : ELLW;
    __syncthreads();

    if (lane == 0) {
        g_diag[erow] = s_diagE[rl];
        g_cnt[erow]  = s_cntE[rl];
    }
    if (tid == 0) {
        float m = s_diagE[0];
#pragma unroll
        for (int i = 1; i < 16; i++) m = fmaxf(m, s_diagE[i]);
        g_bmax[blk] = m;
    }

    // ============ B0: ELL/diag/cnt/hist-zero visible
    grid_barrier();

    // bounds partials + histogram
    {
        const int rc = s_cntE[rl];
        float wsum = 0.f, dnb = 0.f;
        const int2* er = g_ell + (size_t)erow * ELLW;
        for (int k = lane; k < rc; k += 64) {
            int2 e = er[k];
            float dn = g_diag[e.x];
            wsum += __int_as_float(e.y) * dn;
            dnb   = fmaxf(dnb, dn);
        }
#pragma unroll
        for (int off = 16; off; off >>= 1) {
            wsum += __shfl_xor_sync(0xffffffffu, wsum, off);
            dnb   = fmaxf(dnb, __shfl_xor_sync(0xffffffffu, dnb, off));
        }
        if ((lane & 31) == 0) {
            s_red[rl][wir]     = wsum;
            s_red[rl][2 + wir] = dnb;
        }
        if (lane == 0) atomicAdd(&g_hist[rc], 1);
        __syncthreads();
        if (tid == 0) {
            float bm = 0.f, ba = 0.f;
#pragma unroll
            for (int i = 0; i < 16; i++) {
                float du = s_diagE[i];
                float ws = s_red[i][0] + s_red[i][1];
                float nm = fmaxf(s_red[i][2], s_red[i][3]);
                if (du > 1e-20f) bm = fmaxf(bm, du + ws / du);   // Merris
                ba = fmaxf(ba, du + nm);                          // Anderson-Morley
            }
            g_bmer[blk] = bm;
            g_bam [blk] = ba;
        }
    }

    // ============ B1: hist + bounds visible
    grid_barrier();

    // block 0: exclusive prefix of histogram -> g_offs
    if (blk == 0) {
        if (tid < 128) s_scan[tid] = (tid < NB) ? g_hist[tid] : 0;
        __syncthreads();
        for (int off = 1; off < 128; off <<= 1) {
            int v = 0;
            if (tid < 128 && tid >= off) v = s_scan[tid - off];
            __syncthreads();
            if (tid < 128) s_scan[tid] += v;
            __syncthreads();
        }
        if (tid < NB) g_offs[tid] = s_scan[tid] - g_hist[tid];
    }

    // coefficients (every block redundantly; warp 0)
    if (tid < 32) {
        float dm = 0.f, mer = 0.f, am = 0.f;
        for (int i = tid; i < GRID; i += 32) {
            dm  = fmaxf(dm,  g_bmax[i]);
            mer = fmaxf(mer, g_bmer[i]);
            am  = fmaxf(am,  g_bam[i]);
        }
#pragma unroll
        for (int off = 16; off; off >>= 1) {
            dm  = fmaxf(dm,  __shfl_xor_sync(0xffffffffu, dm,  off));
            mer = fmaxf(mer, __shfl_xor_sync(0xffffffffu, mer, off));
            am  = fmaxf(am,  __shfl_xor_sync(0xffffffffu, am,  off));
        }
        double lub = 2.0 * (double)dm;                       // Gershgorin
        double b2  = (double)mer * 1.00001;
        double b3  = (double)am  * 1.00001;
        if (b2 > 1e-12 && b2 < lub) lub = b2;
        if (b3 > 1e-12 && b3 < lub) lub = b3;
        if (lub < 1e-12) lub = 1e-12;

        double tt = (double)fmaxf(t_in[0], 1e-8f);
        double z  = 0.5 * tt * lub;

        const double PI = 3.14159265358979323846;
        double th0 = PI * ((double)tid + 0.5) / 64.0;
        double th1 = PI * ((double)(tid + 32) + 0.5) / 64.0;
        double ct0 = cos(th0), ct1 = cos(th1);
        double f0 = exp(-z * (ct0 + 1.0));
        double f1 = exp(-z * (ct1 + 1.0));
        double cm2_0 = 1.0, cm1_0 = ct0, tc0 = 2.0 * ct0;
        double cm2_1 = 1.0, cm1_1 = ct1, tc1 = 2.0 * ct1;

        for (int k = 0; k <= MMAX; k++) {
            double ck0, ck1;
            if (k == 0)      { ck0 = 1.0; ck1 = 1.0; }
            else if (k == 1) { ck0 = ct0; ck1 = ct1; }
            else {
                ck0 = tc0 * cm1_0 - cm2_0;  cm2_0 = cm1_0;  cm1_0 = ck0;
                ck1 = tc1 * cm1_1 - cm2_1;  cm2_1 = cm1_1;  cm1_1 = ck1;
            }
            double p = f0 * ck0 + f1 * ck1;
#pragma unroll
            for (int off = 16; off; off >>= 1)
                p += __shfl_xor_sync(0xffffffffu, p, off);
            if (tid == 0) {
                double c = (2.0 / 64.0) * p;
                if (k == 0) c *= 0.5;
                s_c[k] = c;
            }
        }
        __syncwarp();
        if (tid == 0) {
            double tail = 0.0;
            int deg = 2;
            for (int k = MMAX; k >= 2; k--) {
                tail += fabs(s_c[k]);
                if (tail > 2e-5) { deg = k; break; }
            }
            if (deg > MMAX) deg = MMAX;
            s_deg = deg;
            s_a   = (float)(4.0 / lub);
            for (int k = 0; k <= MMAX; k++) s_coef[k] = (float)s_c[k];
        }
    }
    __syncthreads();

    // ============ B2: g_offs final
    grid_barrier();

    // rank own rows (assignment order nondeterministic; results row-identical)
    if (lane == 0) {
        int r = atomicAdd(&g_offs[s_cntE[rl]], 1);
        g_perm[r] = erow;
    }

    // ============ B3: perm complete
    grid_barrier();

    // ============ pair setup: group = 128 threads, rows rank G & rank 2047-G
    const int gl = tid >> 7;            // group in block (0..7)
    const int gt = tid & 127;           // thread in group
    const int G  = blk * GPB + gl;
    const int rowA = g_perm[G];
    const int rowB = g_perm[NN - 1 - G];
    const int cA = g_cnt[rowA];
    const int cB = g_cnt[rowB];
    const int tot = cA + cB;
    for (int k = gt; k < cA; k += 128) s_ell[gl][k]      = g_ell[(size_t)rowA * ELLW + k];
    for (int k = gt; k < cB; k += 128) s_ell[gl][cA + k] = g_ell[(size_t)rowB * ELLW + k];
    const float dA = g_diag[rowA];
    const float dB = g_diag[rowB];

    const int ch = gt * 4;                       // lane-contiguous 512B/warp
    const int ridxA = (rowA << 9) + ch;
    const int ridxB = (rowB << 9) + ch;
    const int slotA = gl * 2, slotB = gl * 2 + 1;
    const int ci = ch >> 2;                      // float4 index

    float ykA[4], ykB[4], oA[4], oB[4];
    {
        float4 xa = f4_load(X + ridxA);
        float4 xb = f4_load(X + ridxB);
        ykA[0]=xa.x; ykA[1]=xa.y; ykA[2]=xa.z; ykA[3]=xa.w;
        ykB[0]=xb.x; ykB[1]=xb.y; ykB[2]=xb.z; ykB[3]=xb.w;
    }
    __syncthreads();   // s_ell ready

    const float a   = s_a;
    const int   deg = s_deg;

    // ============ init: T1 = (2/lub)*L@x - x ; out = c0*x + c1*T1
    float accA[4], accB[4];
#pragma unroll
    for (int i = 0; i < 4; i++) { accA[i] = dA * ykA[i]; accB[i] = dB * ykB[i]; }
    spmv_pair(X, ch, s_ell[gl], cA, tot, accA, accB);
    {
        const float ha = 0.5f * a;
        const float c0 = s_coef[0], c1 = s_coef[1];
        float4 pA, pB;
#pragma unroll
        for (int i = 0; i < 4; i++) {
            float t1 = ha * accA[i] - ykA[i];
            oA[i] = c0 * ykA[i] + c1 * t1;
            (&pA.x)[i] = ykA[i];
            ykA[i] = t1;
            float t1b = ha * accB[i] - ykB[i];
            oB[i] = c0 * ykB[i] + c1 * t1b;
            (&pB.x)[i] = ykB[i];
            ykB[i] = t1b;
        }
        s_ykm1[slotA][ci] = pA;   // T0
        s_ykm1[slotB][ci] = pB;
        float4 vA = {ykA[0], ykA[1], ykA[2], ykA[3]};
        float4 vB = {ykB[0], ykB[1], ykB[2], ykB[3]};
        f4_store(g_T1 + ridxA, vA);
        f4_store(g_T1 + ridxB, vB);
    }

    for (int j = 2; j <= deg; j++) {
        grid_barrier();                           // T_{j-1} globally visible
        const float* Tp = (j & 1) ? g_T2 : g_T1;
        float*       Tc = (j & 1) ? g_T1 : g_T2;

#pragma unroll
        for (int i = 0; i < 4; i++) { accA[i] = dA * ykA[i]; accB[i] = dB * ykB[i]; }
        spmv_pair(Tp, ch, s_ell[gl], cA, tot, accA, accB);

        const float c = s_coef[j];
        float4 mA = s_ykm1[slotA][ci];
        float4 mB = s_ykm1[slotB][ci];
        float4 pA, pB, tA, tB;
#pragma unroll
        for (int i = 0; i < 4; i++) {
            float tn = a * accA[i] - 2.f * ykA[i] - (&mA.x)[i];
            oA[i] += c * tn;
            (&pA.x)[i] = ykA[i];
            ykA[i] = tn;
            (&tA.x)[i] = tn;
            float tnb = a * accB[i] - 2.f * ykB[i] - (&mB.x)[i];
            oB[i] += c * tnb;
            (&pB.x)[i] = ykB[i];
            ykB[i] = tnb;
            (&tB.x)[i] = tnb;
        }
        s_ykm1[slotA][ci] = pA;
        s_ykm1[slotB][ci] = pB;
        if (j < deg) {                            // last T never gathered
            f4_store(Tc + ridxA, tA);
            f4_store(Tc + ridxB, tB);
        }
    }

    float4 aA = {oA[0], oA[1], oA[2], oA[3]};
    float4 aB = {oB[0], oB[1], oB[2], oB[3]};
    f4_store(out + ridxA, aA);
    f4_store(out + ridxB, aB);
}

// ---------------------------------------------------------------------------
extern "C" void kernel_launch(void* const* d_in, const int* in_sizes, int n_in,
                              void* d_out, int out_size) {
    const float* x = nullptr;
    const float* L = nullptr;
    const float* t = nullptr;
    for (int i = 0; i < n_in; i++) {
        if      (in_sizes[i] == NN * DD) x = (const float*)d_in[i];
        else if (in_sizes[i] == NN * NN) L = (const float*)d_in[i];
        else if (in_sizes[i] == 1)       t = (const float*)d_in[i];
    }
    float* out = (float*)d_out;

    cheb_all<<<GRID, THREADS>>>(x, L, t, out);
}